// round 9
// baseline (speedup 1.0000x reference)
#include <cuda_runtime.h>
#include <string.h>

// ---------------------------------------------------------------------------
// GraphFeatureTokenizer fused kernel for GB300 (sm_103a) — Round 8
//
// R7 showed occupancy-via-more-splits inflates DRAM (reuse-window spread);
// R3's NSPLIT=3 / TM=8 / 3 CTA/SM structure is traffic-optimal. Its limiter
// is per-warp epilogue MLP (5 loads consumed immediately, 80-reg cap).
// R8: TPB=192 (3 groups of 64), 3 CTAs/SM -> 576 thr/SM -> 113 regs/thread.
// Epilogue batches 4 tokens: all 16 e0..e3 LDG.128s issued into a register
// array (64 regs in flight, MLP~16) before any consumption. order_weight is
// L1-resident (2 rows) and loaded per token. Same-tile L2 prefetch, __stcs,
// fma.rn.f32x2 GEMM unchanged from R3.
// ---------------------------------------------------------------------------

#define HID      768
#define HID4     192              // float4 per row
#define NSPLIT   3
#define SCOLS4   64               // float4 cols per split
#define MAXLEN   15360
#define NB       8
#define SLOTS    (NB * MAXLEN)    // 122880
#define TM       8
#define NTILES   (SLOTS / TM)     // 15360
#define TPB      192
#define NGRP     3
#define GSZ      64
#define NWORK    152

#define F_ELEMS  (SLOTS * HID)    // 94371840
#define M_ELEMS  (SLOTS)          // 122880
#define I_ELEMS  (SLOTS * 2)      // 245760

#define SM_W_FLOATS   (64 * 256)              // 16384 floats = 64KB
#define SM_IE_FLOATS  (NGRP * TM * 64)        // 1536
#define SM_META_INTS  (NGRP * TM * 5)         // 120
#define SM_OFF_INTS   32
#define SMEM_BYTES    ((SM_W_FLOATS + SM_IE_FLOATS) * 4 + (SM_META_INTS + SM_OFF_INTS) * 4)

typedef unsigned long long ull;

__device__ __forceinline__ ull pack2(float x) {
    float2 q = make_float2(x, x);
    ull r; memcpy(&r, &q, 8);
    return r;
}
__device__ __forceinline__ float2 unpack2(ull v) {
    float2 r; memcpy(&r, &v, 8);
    return r;
}
__device__ __forceinline__ ull lo2(float4 w) {
    float2 q = make_float2(w.x, w.y);
    ull r; memcpy(&r, &q, 8);
    return r;
}
__device__ __forceinline__ ull hi2(float4 w) {
    float2 q = make_float2(w.z, w.w);
    ull r; memcpy(&r, &q, 8);
    return r;
}
__device__ __forceinline__ void fma2(ull& acc, ull a, ull b) {
    asm("fma.rn.f32x2 %0, %1, %2, %0;" : "+l"(acc) : "l"(a), "l"(b));
}
__device__ __forceinline__ void pf_l2(const void* p) {
    asm volatile("prefetch.global.L2 [%0];" :: "l"(p));
}

extern "C" __global__ void __launch_bounds__(TPB, 3)
gft_kernel(const float* __restrict__ embedW,
           const float* __restrict__ lapW,
           const float* __restrict__ orderW,
           const float* __restrict__ eig,
           const int*   __restrict__ nodeData,
           const int*   __restrict__ edgeData,
           const int*   __restrict__ edgeIndex,
           const int*   __restrict__ nodeNum,
           const int*   __restrict__ edgeNum,
           float*       __restrict__ out,
           int Etot, int extraMode)
{
    extern __shared__ float smem[];
    float4* sW4   = (float4*)smem;                        // [64 k][64 c4]
    float*  sIE   = smem + SM_W_FLOATS;                   // [NGRP][TM][64]
    int*    sMeta = (int*)(sIE + SM_IE_FLOATS);           // [NGRP][TM][5]
    int*    sOff  = sMeta + SM_META_INTS;                 // [32]

    const int tid    = threadIdx.x;
    const int nwork  = gridDim.x / NSPLIT;
    const int split  = blockIdx.x / nwork;                // 0..2
    const int worker = blockIdx.x - split * nwork;

    // --- init: weight slice -> smem, prefix sums ---
    {
        const float4* s = (const float4*)lapW;
        #pragma unroll 4
        for (int i = tid; i < 64 * SCOLS4; i += TPB) {
            const int k = i >> 6, c4 = i & 63;
            sW4[i] = s[k * HID4 + split * SCOLS4 + c4];
        }
    }
    if (tid < NB) {
        int no = 0, eo = 0;
        for (int x = 0; x < tid; x++) { no += nodeNum[x]; eo += edgeNum[x]; }
        sOff[tid]      = no;
        sOff[8 + tid]  = eo;
        sOff[16 + tid] = nodeNum[tid];
        sOff[24 + tid] = nodeNum[tid] + edgeNum[tid];
    }
    __syncthreads();

    const int g  = tid >> 6;                 // group 0..2
    const int lt = tid & 63;
    float* gIE   = sIE + g * TM * 64;
    int*   gMeta = sMeta + g * TM * 5;
    const int barid = 1 + g;
    const int grp   = worker * NGRP + g;
    const int ngrp  = nwork * NGRP;
    const int cb4   = split * SCOLS4 + lt;   // thread's float4 col

    for (int tile = grp; tile < NTILES; tile += ngrp) {
        const int slot0 = tile * TM;
        const int b  = slot0 / MAXLEN;
        const int t0 = slot0 - b * MAXLEN;
        const int nOff = sOff[b], eOff = sOff[8 + b];
        const int nn = sOff[16 + b], seq = sOff[24 + b];

        if (t0 >= seq) {
            if (split == 0 && lt < TM && extraMode) {
                const int slot = slot0 + lt;
                if (extraMode == 1) {
                    out[(size_t)F_ELEMS + slot] = 1.0f;
                    out[(size_t)F_ELEMS + M_ELEMS + 2 * slot]     = 0.0f;
                    out[(size_t)F_ELEMS + M_ELEMS + 2 * slot + 1] = 0.0f;
                } else {
                    ((unsigned char*)out)[(size_t)F_ELEMS * 4 + slot] = 1;
                    int* ip = (int*)((char*)out + (size_t)F_ELEMS * 4 + M_ELEMS);
                    ip[2 * slot] = 0; ip[2 * slot + 1] = 0;
                }
            }
            const float4 z = make_float4(0.f, 0.f, 0.f, 0.f);
            #pragma unroll
            for (int m = 0; m < TM; m++)
                __stcs((float4*)out + (size_t)(slot0 + m) * HID4 + cb4, z);
            continue;
        }

        // --- phase A: metadata (lanes 0..7), same-tile L2 prefetch, ie ---
        if (lt < TM) {
            const int m = lt, t = t0 + m;
            int r0 = 0, r1 = 0, r2 = 0, r3 = 0, ord = 1, i0 = 0, i1 = 0;
            const bool pad = (t >= seq);
            if (!pad) {
                if (t < nn) {
                    int4 rr = ((const int4*)nodeData)[nOff + t];
                    r0 = rr.x; r1 = rr.y; r2 = rr.z; r3 = rr.w;
                    i0 = t; i1 = t; ord = 1;
                } else {
                    const int ge = eOff + (t - nn);
                    int4 rr = ((const int4*)edgeData)[ge];
                    r0 = rr.x; r1 = rr.y; r2 = rr.z; r3 = rr.w;
                    i0 = edgeIndex[ge]; i1 = edgeIndex[Etot + ge];
                    ord = (i0 == i1) ? 1 : 0;
                }
            }
            gMeta[m * 5 + 0] = r0; gMeta[m * 5 + 1] = r1;
            gMeta[m * 5 + 2] = r2; gMeta[m * 5 + 3] = r3;
            gMeta[m * 5 + 4] = ord;
            if (split == 0 && extraMode) {
                const int slot = slot0 + m;
                if (extraMode == 1) {
                    out[(size_t)F_ELEMS + slot] = pad ? 1.0f : 0.0f;
                    out[(size_t)F_ELEMS + M_ELEMS + 2 * slot]     = (float)i0;
                    out[(size_t)F_ELEMS + M_ELEMS + 2 * slot + 1] = (float)i1;
                } else {
                    ((unsigned char*)out)[(size_t)F_ELEMS * 4 + slot] = pad ? 1 : 0;
                    int* ip = (int*)((char*)out + (size_t)F_ELEMS * 4 + M_ELEMS);
                    ip[2 * slot] = i0; ip[2 * slot + 1] = i1;
                }
            }
        }
        {
            // L2 prefetch (same-tile, proven distance): thread (m = lt>>3,
            // j = lt&7): line j of token m's 4 embed rows (1KB slice).
            const int m = lt >> 3, j = lt & 7;
            const int t = t0 + m;
            if (t < seq) {
                int4 rr;
                if (t < nn) rr = ((const int4*)nodeData)[nOff + t];
                else        rr = ((const int4*)edgeData)[eOff + (t - nn)];
                const char* eb = (const char*)embedW + (size_t)split * 1024 + j * 128;
                pf_l2(eb + (size_t)rr.x * 3072);
                pf_l2(eb + (size_t)rr.y * 3072);
                pf_l2(eb + (size_t)rr.z * 3072);
                pf_l2(eb + (size_t)rr.w * 3072);
            }
        }
        {
            // ie gather: thread fills 8 consecutive j's of one token's ie[64]
            const int m = lt >> 3;
            const int jbase = (lt & 7) * 8;
            const int t = t0 + m;
            const bool pad = (t >= seq);
            int row = 0;
            if (!pad) {
                if (t < nn) row = nOff + t;
                else {
                    const int ge = eOff + (t - nn);
                    row = nOff + ((jbase < 32) ? edgeIndex[ge] : edgeIndex[Etot + ge]);
                }
            }
            const int jj = jbase & 31;
            const float4* er4 = (const float4*)(eig + (size_t)row * 32 + jj);
            float4 v0, v1;
            if (pad) { v0 = make_float4(0,0,0,0); v1 = v0; }
            else     { v0 = er4[0]; v1 = er4[1]; }
            float4* dst = (float4*)(gIE + m * 64 + jbase);
            dst[0] = v0; dst[1] = v1;
        }
        asm volatile("bar.sync %0, %1;" :: "r"(barid), "r"(GSZ) : "memory");

        // --- phase B: GEMM ie[8][64] @ Wslice[64][256] ---
        ull acc[TM][2];
        #pragma unroll
        for (int m = 0; m < TM; m++) { acc[m][0] = 0ull; acc[m][1] = 0ull; }

        #pragma unroll 2
        for (int kq = 0; kq < 16; kq++) {
            float4 w0 = sW4[(4 * kq + 0) * SCOLS4 + lt];
            float4 w1 = sW4[(4 * kq + 1) * SCOLS4 + lt];
            float4 w2 = sW4[(4 * kq + 2) * SCOLS4 + lt];
            float4 w3 = sW4[(4 * kq + 3) * SCOLS4 + lt];
            const ull w0l = lo2(w0), w0h = hi2(w0);
            const ull w1l = lo2(w1), w1h = hi2(w1);
            const ull w2l = lo2(w2), w2h = hi2(w2);
            const ull w3l = lo2(w3), w3h = hi2(w3);
            #pragma unroll
            for (int m = 0; m < TM; m++) {
                const float4 p = ((const float4*)(gIE + m * 64))[kq];
                const ull x0 = pack2(p.x), x1 = pack2(p.y);
                const ull x2 = pack2(p.z), x3 = pack2(p.w);
                fma2(acc[m][0], x0, w0l); fma2(acc[m][1], x0, w0h);
                fma2(acc[m][0], x1, w1l); fma2(acc[m][1], x1, w1h);
                fma2(acc[m][0], x2, w2l); fma2(acc[m][1], x2, w2h);
                fma2(acc[m][0], x3, w3l); fma2(acc[m][1], x3, w3h);
            }
        }

        // --- phase C: BATCHED embed gather (MLP~16) + order + store ---
        const float4* em4 = (const float4*)embedW;
        const float4* ow4 = (const float4*)orderW;
        #pragma unroll
        for (int h = 0; h < 2; h++) {
            // issue all 16 embed loads for tokens [4h, 4h+4) first
            float4 eb[4][4];
            #pragma unroll
            for (int mm = 0; mm < 4; mm++) {
                const int m = h * 4 + mm;
                const int t = t0 + m;
                const bool ok = (t < seq);
                const int r0 = ok ? gMeta[m * 5 + 0] : 0;
                const int r1 = ok ? gMeta[m * 5 + 1] : 0;
                const int r2 = ok ? gMeta[m * 5 + 2] : 0;
                const int r3 = ok ? gMeta[m * 5 + 3] : 0;
                eb[mm][0] = em4[(size_t)r0 * HID4 + cb4];
                eb[mm][1] = em4[(size_t)r1 * HID4 + cb4];
                eb[mm][2] = em4[(size_t)r2 * HID4 + cb4];
                eb[mm][3] = em4[(size_t)r3 * HID4 + cb4];
            }
            // consume
            #pragma unroll
            for (int mm = 0; mm < 4; mm++) {
                const int m = h * 4 + mm;
                const int t = t0 + m;
                float4* o4 = (float4*)out + (size_t)(slot0 + m) * HID4 + cb4;
                if (t >= seq) {
                    __stcs(o4, make_float4(0.f, 0.f, 0.f, 0.f));
                } else {
                    const int ord = gMeta[m * 5 + 4];
                    const float4 w = ow4[(size_t)ord * HID4 + cb4];  // L1-hot
                    const float2 a0 = unpack2(acc[m][0]);
                    const float2 a1 = unpack2(acc[m][1]);
                    float4 v;
                    v.x = a0.x + eb[mm][0].x + eb[mm][1].x + eb[mm][2].x + eb[mm][3].x + w.x;
                    v.y = a0.y + eb[mm][0].y + eb[mm][1].y + eb[mm][2].y + eb[mm][3].y + w.y;
                    v.z = a1.x + eb[mm][0].z + eb[mm][1].z + eb[mm][2].z + eb[mm][3].z + w.z;
                    v.w = a1.y + eb[mm][0].w + eb[mm][1].w + eb[mm][2].w + eb[mm][3].w + w.w;
                    __stcs(o4, v);
                }
            }
        }
        asm volatile("bar.sync %0, %1;" :: "r"(barid), "r"(GSZ) : "memory");
    }
}

extern "C" void kernel_launch(void* const* d_in, const int* in_sizes, int n_in,
                              void* d_out, int out_size)
{
    const float* embedW   = (const float*)d_in[0];
    const float* lapW     = (const float*)d_in[1];
    const float* orderW   = (const float*)d_in[2];
    const float* eig      = (const float*)d_in[3];
    const int*   nodeData = (const int*)d_in[4];
    const int*   edgeData = (const int*)d_in[5];
    const int*   edgeIdx  = (const int*)d_in[6];
    const int*   nodeNum  = (const int*)d_in[7];
    const int*   edgeNum  = (const int*)d_in[8];

    const int Etot = in_sizes[6] / 2;

    int extraMode = 0;
    const long long allF  = (long long)F_ELEMS + M_ELEMS + I_ELEMS;           // 94740480
    const long long rawB  = (long long)F_ELEMS + (M_ELEMS + I_ELEMS * 4) / 4; // 94648320
    if ((long long)out_size == allF)      extraMode = 1;
    else if ((long long)out_size == rawB) extraMode = 2;

    cudaFuncSetAttribute(gft_kernel, cudaFuncAttributeMaxDynamicSharedMemorySize, SMEM_BYTES);
    gft_kernel<<<NWORK * NSPLIT, TPB, SMEM_BYTES>>>(embedW, lapW, orderW, eig,
                                                    nodeData, edgeData, edgeIdx,
                                                    nodeNum, edgeNum,
                                                    (float*)d_out, Etot, extraMode);
}

// round 10
// speedup vs baseline: 1.1624x; 1.1624x over previous
#include <cuda_runtime.h>
#include <string.h>

// ---------------------------------------------------------------------------
// GraphFeatureTokenizer fused kernel for GB300 (sm_103a) — Round 9
//
// Base = R3 (best, 307.7us): NSPLIT=3 x 256 cols, TM=8, 3 CTAs/SM (24 warps),
// fma.rn.f32x2 GEMM, same-tile L2 prefetch, __stcs streaming output.
// R9 change (single mechanism): the embed table (154MB) nearly fits in L2
// (126MB) and every row is reused ~7.8x, but measured hit rate was only ~39%
// (lines churned before reuse). Phase-C embed loads now use an
// L2::evict_last cache policy (createpolicy.fractional + ld.L2::cache_hint)
// so table lines are retained preferentially; the output stream is already
// evict-first (__stcs). Expect embed DRAM re-fetch to drop ~2x.
// ---------------------------------------------------------------------------

#define HID      768
#define HID4     192              // float4 per row
#define NSPLIT   3
#define SCOLS4   64               // float4 cols per split
#define MAXLEN   15360
#define NB       8
#define SLOTS    (NB * MAXLEN)    // 122880
#define TM       8
#define NTILES   (SLOTS / TM)     // 15360
#define TPB      256
#define NGRP     4
#define GSZ      64
#define NWORK    152

#define F_ELEMS  (SLOTS * HID)    // 94371840
#define M_ELEMS  (SLOTS)          // 122880
#define I_ELEMS  (SLOTS * 2)      // 245760

#define SM_W_FLOATS   (64 * 256)              // 16384 floats = 64KB
#define SM_IE_FLOATS  (NGRP * TM * 64)        // 2048
#define SM_META_INTS  (NGRP * TM * 5)         // 160
#define SM_OFF_INTS   32
#define SMEM_BYTES    ((SM_W_FLOATS + SM_IE_FLOATS) * 4 + (SM_META_INTS + SM_OFF_INTS) * 4)

typedef unsigned long long ull;

__device__ __forceinline__ ull pack2(float x) {
    float2 q = make_float2(x, x);
    ull r; memcpy(&r, &q, 8);
    return r;
}
__device__ __forceinline__ float2 unpack2(ull v) {
    float2 r; memcpy(&r, &v, 8);
    return r;
}
__device__ __forceinline__ ull lo2(float4 w) {
    float2 q = make_float2(w.x, w.y);
    ull r; memcpy(&r, &q, 8);
    return r;
}
__device__ __forceinline__ ull hi2(float4 w) {
    float2 q = make_float2(w.z, w.w);
    ull r; memcpy(&r, &q, 8);
    return r;
}
__device__ __forceinline__ void fma2(ull& acc, ull a, ull b) {
    asm("fma.rn.f32x2 %0, %1, %2, %0;" : "+l"(acc) : "l"(a), "l"(b));
}
__device__ __forceinline__ void pf_l2(const void* p) {
    asm volatile("prefetch.global.L2 [%0];" :: "l"(p));
}
// float4 load with an L2 cache-policy hint (evict_last for the embed table)
__device__ __forceinline__ float4 ld4_pol(const float4* p, ull pol) {
    float4 v;
    asm("ld.global.L2::cache_hint.v4.f32 {%0,%1,%2,%3}, [%4], %5;"
        : "=f"(v.x), "=f"(v.y), "=f"(v.z), "=f"(v.w)
        : "l"(p), "l"(pol));
    return v;
}

extern "C" __global__ void __launch_bounds__(TPB, 3)
gft_kernel(const float* __restrict__ embedW,
           const float* __restrict__ lapW,
           const float* __restrict__ orderW,
           const float* __restrict__ eig,
           const int*   __restrict__ nodeData,
           const int*   __restrict__ edgeData,
           const int*   __restrict__ edgeIndex,
           const int*   __restrict__ nodeNum,
           const int*   __restrict__ edgeNum,
           float*       __restrict__ out,
           int Etot, int extraMode)
{
    extern __shared__ float smem[];
    float4* sW4   = (float4*)smem;                        // [64 k][64 c4]
    float*  sIE   = smem + SM_W_FLOATS;                   // [NGRP][TM][64]
    int*    sMeta = (int*)(sIE + SM_IE_FLOATS);           // [NGRP][TM][5]
    int*    sOff  = sMeta + SM_META_INTS;                 // [32]

    const int tid    = threadIdx.x;
    const int nwork  = gridDim.x / NSPLIT;
    const int split  = blockIdx.x / nwork;                // 0..2
    const int worker = blockIdx.x - split * nwork;

    // L2 retention policy for the embed table
    ull polEL;
    asm("createpolicy.fractional.L2::evict_last.b64 %0, 1.0;" : "=l"(polEL));

    // --- init: weight slice -> smem, prefix sums ---
    {
        const float4* s = (const float4*)lapW;
        #pragma unroll 4
        for (int i = tid; i < 64 * SCOLS4; i += TPB) {
            const int k = i >> 6, c4 = i & 63;
            sW4[i] = s[k * HID4 + split * SCOLS4 + c4];
        }
    }
    if (tid < NB) {
        int no = 0, eo = 0;
        for (int x = 0; x < tid; x++) { no += nodeNum[x]; eo += edgeNum[x]; }
        sOff[tid]      = no;
        sOff[8 + tid]  = eo;
        sOff[16 + tid] = nodeNum[tid];
        sOff[24 + tid] = nodeNum[tid] + edgeNum[tid];
    }
    __syncthreads();

    const int g  = tid >> 6;
    const int lt = tid & 63;
    float* gIE   = sIE + g * TM * 64;
    int*   gMeta = sMeta + g * TM * 5;
    const int barid = 1 + g;
    const int grp   = worker * NGRP + g;
    const int ngrp  = nwork * NGRP;
    const int cb4   = split * SCOLS4 + lt;                // thread's float4 col

    for (int tile = grp; tile < NTILES; tile += ngrp) {
        const int slot0 = tile * TM;
        const int b  = slot0 / MAXLEN;
        const int t0 = slot0 - b * MAXLEN;
        const int nOff = sOff[b], eOff = sOff[8 + b];
        const int nn = sOff[16 + b], seq = sOff[24 + b];

        if (t0 >= seq) {
            if (split == 0 && lt < TM && extraMode) {
                const int slot = slot0 + lt;
                if (extraMode == 1) {
                    out[(size_t)F_ELEMS + slot] = 1.0f;
                    out[(size_t)F_ELEMS + M_ELEMS + 2 * slot]     = 0.0f;
                    out[(size_t)F_ELEMS + M_ELEMS + 2 * slot + 1] = 0.0f;
                } else {
                    ((unsigned char*)out)[(size_t)F_ELEMS * 4 + slot] = 1;
                    int* ip = (int*)((char*)out + (size_t)F_ELEMS * 4 + M_ELEMS);
                    ip[2 * slot] = 0; ip[2 * slot + 1] = 0;
                }
            }
            const float4 z = make_float4(0.f, 0.f, 0.f, 0.f);
            #pragma unroll
            for (int m = 0; m < TM; m++)
                __stcs((float4*)out + (size_t)(slot0 + m) * HID4 + cb4, z);
            continue;
        }

        // --- phase A: metadata (lanes 0..7), same-tile L2 prefetch, ie ---
        if (lt < TM) {
            const int m = lt, t = t0 + m;
            int r0 = 0, r1 = 0, r2 = 0, r3 = 0, ord = 1, i0 = 0, i1 = 0;
            const bool pad = (t >= seq);
            if (!pad) {
                if (t < nn) {
                    int4 rr = ((const int4*)nodeData)[nOff + t];
                    r0 = rr.x; r1 = rr.y; r2 = rr.z; r3 = rr.w;
                    i0 = t; i1 = t; ord = 1;
                } else {
                    const int ge = eOff + (t - nn);
                    int4 rr = ((const int4*)edgeData)[ge];
                    r0 = rr.x; r1 = rr.y; r2 = rr.z; r3 = rr.w;
                    i0 = edgeIndex[ge]; i1 = edgeIndex[Etot + ge];
                    ord = (i0 == i1) ? 1 : 0;
                }
            }
            gMeta[m * 5 + 0] = r0; gMeta[m * 5 + 1] = r1;
            gMeta[m * 5 + 2] = r2; gMeta[m * 5 + 3] = r3;
            gMeta[m * 5 + 4] = ord;
            if (split == 0 && extraMode) {
                const int slot = slot0 + m;
                if (extraMode == 1) {
                    out[(size_t)F_ELEMS + slot] = pad ? 1.0f : 0.0f;
                    out[(size_t)F_ELEMS + M_ELEMS + 2 * slot]     = (float)i0;
                    out[(size_t)F_ELEMS + M_ELEMS + 2 * slot + 1] = (float)i1;
                } else {
                    ((unsigned char*)out)[(size_t)F_ELEMS * 4 + slot] = pad ? 1 : 0;
                    int* ip = (int*)((char*)out + (size_t)F_ELEMS * 4 + M_ELEMS);
                    ip[2 * slot] = i0; ip[2 * slot + 1] = i1;
                }
            }
        }
        {
            // L2 prefetch (same-tile distance, proven in R3): thread
            // (m = lt>>3, j = lt&7) warms line j of token m's 4 embed rows.
            const int m = lt >> 3, j = lt & 7;
            const int t = t0 + m;
            if (t < seq) {
                int4 rr;
                if (t < nn) rr = ((const int4*)nodeData)[nOff + t];
                else        rr = ((const int4*)edgeData)[eOff + (t - nn)];
                const char* eb = (const char*)embedW + (size_t)split * 1024 + j * 128;
                pf_l2(eb + (size_t)rr.x * 3072);
                pf_l2(eb + (size_t)rr.y * 3072);
                pf_l2(eb + (size_t)rr.z * 3072);
                pf_l2(eb + (size_t)rr.w * 3072);
            }
        }
        {
            // ie gather: thread fills 8 consecutive j's of one token's ie[64]
            const int m = lt >> 3;
            const int jbase = (lt & 7) * 8;
            const int t = t0 + m;
            const bool pad = (t >= seq);
            int row = 0;
            if (!pad) {
                if (t < nn) row = nOff + t;
                else {
                    const int ge = eOff + (t - nn);
                    row = nOff + ((jbase < 32) ? edgeIndex[ge] : edgeIndex[Etot + ge]);
                }
            }
            const int jj = jbase & 31;
            const float4* er4 = (const float4*)(eig + (size_t)row * 32 + jj);
            float4 v0, v1;
            if (pad) { v0 = make_float4(0,0,0,0); v1 = v0; }
            else     { v0 = er4[0]; v1 = er4[1]; }
            float4* dst = (float4*)(gIE + m * 64 + jbase);
            dst[0] = v0; dst[1] = v1;
        }
        asm volatile("bar.sync %0, %1;" :: "r"(barid), "r"(GSZ) : "memory");

        // --- phase B: GEMM ie[8][64] @ Wslice[64][256], 128-bit LDS ---
        ull acc[TM][2];
        #pragma unroll
        for (int m = 0; m < TM; m++) { acc[m][0] = 0ull; acc[m][1] = 0ull; }

        #pragma unroll 2
        for (int kq = 0; kq < 16; kq++) {
            float4 w0 = sW4[(4 * kq + 0) * SCOLS4 + lt];
            float4 w1 = sW4[(4 * kq + 1) * SCOLS4 + lt];
            float4 w2 = sW4[(4 * kq + 2) * SCOLS4 + lt];
            float4 w3 = sW4[(4 * kq + 3) * SCOLS4 + lt];
            const ull w0l = lo2(w0), w0h = hi2(w0);
            const ull w1l = lo2(w1), w1h = hi2(w1);
            const ull w2l = lo2(w2), w2h = hi2(w2);
            const ull w3l = lo2(w3), w3h = hi2(w3);
            #pragma unroll
            for (int m = 0; m < TM; m++) {
                const float4 p = ((const float4*)(gIE + m * 64))[kq];
                const ull x0 = pack2(p.x), x1 = pack2(p.y);
                const ull x2 = pack2(p.z), x3 = pack2(p.w);
                fma2(acc[m][0], x0, w0l); fma2(acc[m][1], x0, w0h);
                fma2(acc[m][0], x1, w1l); fma2(acc[m][1], x1, w1h);
                fma2(acc[m][0], x2, w2l); fma2(acc[m][1], x2, w2h);
                fma2(acc[m][0], x3, w3l); fma2(acc[m][1], x3, w3h);
            }
        }

        // --- phase C: embed gather with L2 evict_last + order + store ---
        const float4* em4 = (const float4*)embedW;
        const float4* ow4 = (const float4*)orderW;
        #pragma unroll
        for (int m = 0; m < TM; m++) {
            const int t = t0 + m;
            float4* o4 = (float4*)out + (size_t)(slot0 + m) * HID4 + cb4;
            if (t >= seq) {
                __stcs(o4, make_float4(0.f, 0.f, 0.f, 0.f));
            } else {
                const int r0 = gMeta[m * 5 + 0], r1 = gMeta[m * 5 + 1];
                const int r2 = gMeta[m * 5 + 2], r3 = gMeta[m * 5 + 3];
                const int ord = gMeta[m * 5 + 4];
                const float4 e0 = ld4_pol(em4 + (size_t)r0 * HID4 + cb4, polEL);
                const float4 e1 = ld4_pol(em4 + (size_t)r1 * HID4 + cb4, polEL);
                const float4 e2 = ld4_pol(em4 + (size_t)r2 * HID4 + cb4, polEL);
                const float4 e3 = ld4_pol(em4 + (size_t)r3 * HID4 + cb4, polEL);
                const float4 w  = ow4[(size_t)ord * HID4 + cb4];
                const float2 a0 = unpack2(acc[m][0]);
                const float2 a1 = unpack2(acc[m][1]);
                float4 v;
                v.x = a0.x + e0.x + e1.x + e2.x + e3.x + w.x;
                v.y = a0.y + e0.y + e1.y + e2.y + e3.y + w.y;
                v.z = a1.x + e0.z + e1.z + e2.z + e3.z + w.z;
                v.w = a1.y + e0.w + e1.w + e2.w + e3.w + w.w;
                __stcs(o4, v);
            }
        }
        asm volatile("bar.sync %0, %1;" :: "r"(barid), "r"(GSZ) : "memory");
    }
}

extern "C" void kernel_launch(void* const* d_in, const int* in_sizes, int n_in,
                              void* d_out, int out_size)
{
    const float* embedW   = (const float*)d_in[0];
    const float* lapW     = (const float*)d_in[1];
    const float* orderW   = (const float*)d_in[2];
    const float* eig      = (const float*)d_in[3];
    const int*   nodeData = (const int*)d_in[4];
    const int*   edgeData = (const int*)d_in[5];
    const int*   edgeIdx  = (const int*)d_in[6];
    const int*   nodeNum  = (const int*)d_in[7];
    const int*   edgeNum  = (const int*)d_in[8];

    const int Etot = in_sizes[6] / 2;

    int extraMode = 0;
    const long long allF  = (long long)F_ELEMS + M_ELEMS + I_ELEMS;           // 94740480
    const long long rawB  = (long long)F_ELEMS + (M_ELEMS + I_ELEMS * 4) / 4; // 94648320
    if ((long long)out_size == allF)      extraMode = 1;
    else if ((long long)out_size == rawB) extraMode = 2;

    cudaFuncSetAttribute(gft_kernel, cudaFuncAttributeMaxDynamicSharedMemorySize, SMEM_BYTES);
    gft_kernel<<<NWORK * NSPLIT, TPB, SMEM_BYTES>>>(embedW, lapW, orderW, eig,
                                                    nodeData, edgeData, edgeIdx,
                                                    nodeNum, edgeNum,
                                                    (float*)d_out, Etot, extraMode);
}